// round 11
// baseline (speedup 1.0000x reference)
#include <cuda_runtime.h>
#include <cuda_fp16.h>
#include <math.h>
#include <stdint.h>

// Problem constants
#define NB 4096
#define ND 128
#define EPSF 1e-8f
#define TEMPF 11.313708498984761f   // sqrt(128)

// Scratch (device globals; no allocation allowed)
__device__ __half g_xq_hi[NB * ND];
__device__ __half g_xq_lo[NB * ND];
__device__ __half g_xk_hi[NB * ND];
__device__ __half g_xk_lo[NB * ND];
__device__ __half g_wq_hi[ND * ND];
__device__ __half g_wq_lo[ND * ND];
__device__ __half g_wk_hi[ND * ND];
__device__ __half g_wk_lo[ND * ND];
__device__ __half g_qn_hi[NB * ND];
__device__ __half g_kn_hi[NB * ND];
__device__ float g_qsq[NB];
__device__ float g_ksq[NB];
__device__ float g_psum[NB * 64];     // per-(row, jblock-half) partial row sums
__device__ unsigned g_tile_ctr;       // phase-1 ticket
__device__ unsigned g_done_ctr;       // grid-sync arrival counter

// ---------------------------------------------------------------------------
// PTX helpers (base compute_103 — NO sm_103a-only instructions)
// ---------------------------------------------------------------------------
__device__ __forceinline__ uint32_t smem_u32(const void* p) {
    uint32_t a;
    asm("{ .reg .u64 t; cvta.to.shared.u64 t, %1; cvt.u32.u64 %0, t; }"
        : "=r"(a) : "l"(p));
    return a;
}

__device__ __forceinline__ void ldsm4(uint32_t* r, uint32_t addr) {
    asm volatile("ldmatrix.sync.aligned.m8n8.x4.shared.b16 {%0,%1,%2,%3}, [%4];"
                 : "=r"(r[0]), "=r"(r[1]), "=r"(r[2]), "=r"(r[3]) : "r"(addr));
}

__device__ __forceinline__ void mma_f16(float* c, const uint32_t* a,
                                        const uint32_t* b) {
    asm volatile(
        "mma.sync.aligned.m16n8k16.row.col.f32.f16.f16.f32 "
        "{%0,%1,%2,%3}, {%4,%5,%6,%7}, {%8,%9}, {%0,%1,%2,%3};"
        : "+f"(c[0]), "+f"(c[1]), "+f"(c[2]), "+f"(c[3])
        : "r"(a[0]), "r"(a[1]), "r"(a[2]), "r"(a[3]), "r"(b[0]), "r"(b[1]));
}

__device__ __forceinline__ void cp16(uint32_t s, const void* g) {
    asm volatile("cp.async.cg.shared.global [%0], [%1], 16;" :: "r"(s), "l"(g));
}
__device__ __forceinline__ void cp_commit() {
    asm volatile("cp.async.commit_group;" ::: "memory");
}
__device__ __forceinline__ void cp_wait1() {
    asm volatile("cp.async.wait_group 1;" ::: "memory");
}
__device__ __forceinline__ void cp_wait0() {
    asm volatile("cp.async.wait_group 0;" ::: "memory");
}

__device__ __forceinline__ uint32_t pack_h2(__half a, __half b) {
    __half2 t(a, b);
    return *reinterpret_cast<uint32_t*>(&t);
}

// fast approx sqrt (1 MUFU op; ~2^-21 rel err; sqrt.approx(0)=0)
__device__ __forceinline__ float fsqrt_ap(float x) {
    float r;
    asm("sqrt.approx.f32 %0, %1;" : "=f"(r) : "f"(x));
    return r;
}

// ---------------------------------------------------------------------------
// Kernel 0: fp32 -> fp16 hi/lo split of X (q,k) and W (q,k) + counter reset.
// ---------------------------------------------------------------------------
__global__ __launch_bounds__(256) void split_kernel(
    const float* __restrict__ qp, const float* __restrict__ kp,
    const float* __restrict__ Wq, const float* __restrict__ Wk)
{
    const int idx = blockIdx.x * 256 + threadIdx.x;
    if (idx == 0) { g_tile_ctr = 0u; g_done_ctr = 0u; }

    const float* src;
    __half *hi, *lo;
    int off;
    if (idx < 131072)      { src = qp; hi = g_xq_hi; lo = g_xq_lo; off = idx; }
    else if (idx < 262144) { src = kp; hi = g_xk_hi; lo = g_xk_lo; off = idx - 131072; }
    else if (idx < 266240) { src = Wq; hi = g_wq_hi; lo = g_wq_lo; off = idx - 262144; }
    else                   { src = Wk; hi = g_wk_hi; lo = g_wk_lo; off = idx - 266240; }

    const float4 v = ((const float4*)src)[off];
    const __half h0 = __float2half(v.x), h1 = __float2half(v.y);
    const __half h2 = __float2half(v.z), h3 = __float2half(v.w);
    const __half l0 = __float2half(v.x - __half2float(h0));
    const __half l1 = __float2half(v.y - __half2float(h1));
    const __half l2 = __float2half(v.z - __half2float(h2));
    const __half l3 = __float2half(v.w - __half2float(h3));
    ((uint2*)hi)[off] = make_uint2(pack_h2(h0, h1), pack_h2(h2, h3));
    ((uint2*)lo)[off] = make_uint2(pack_h2(l0, l1), pack_h2(l2, l3));
}

// ---------------------------------------------------------------------------
// Shared tile-layout constants
// ---------------------------------------------------------------------------
#define SSTRIDE 40                 // fp16 elems per smem row (80 B)
#define MAT_BYTES 10240            // 128 rows * 80 B

// ---------------------------------------------------------------------------
// Kernel A: projection via compensated HMMA + analytic metric normalization.
// ---------------------------------------------------------------------------
#define PSTAGE_BYTES (4 * MAT_BYTES)
#define PROJ_SMEM (2 * PSTAGE_BYTES)   // 81920

__device__ __forceinline__ void proj_issue(uint32_t sbase, int st, int kc,
                                           int i0, int which, int tid)
{
    const __half* xh = which ? g_xk_hi : g_xq_hi;
    const __half* xl = which ? g_xk_lo : g_xq_lo;
    const __half* wh = which ? g_wk_hi : g_wq_hi;
    const __half* wl = which ? g_wk_lo : g_wq_lo;
    const uint32_t stb = sbase + (uint32_t)(st * PSTAGE_BYTES);
#pragma unroll
    for (int it = 0; it < 2; it++) {
        const int t = it * 256 + tid;
        const int row = t >> 2;
        const int seg = t & 3;
        const uint32_t soff = (uint32_t)(row * 80 + seg * 16);
        const size_t gx = (size_t)(i0 + row) * ND + kc * 32 + seg * 8;
        const size_t gw = (size_t)row * ND + kc * 32 + seg * 8;
        cp16(stb + 0 * MAT_BYTES + soff, &xh[gx]);
        cp16(stb + 1 * MAT_BYTES + soff, &xl[gx]);
        cp16(stb + 2 * MAT_BYTES + soff, &wh[gw]);
        cp16(stb + 3 * MAT_BYTES + soff, &wl[gw]);
    }
}

__global__ __launch_bounds__(256) void proj_mma_kernel(
    const float* __restrict__ bq, const float* __restrict__ bk)
{
    extern __shared__ __align__(16) char dsm[];
    __shared__ float b_s[128];

    const int tid = threadIdx.x;
    const int lane = tid & 31;
    const int w = tid >> 5;
    const int which = blockIdx.y;
    const int i0 = blockIdx.x * 128;

    if (tid < 128) b_s[tid] = which ? bk[tid] : bq[tid];

    const uint32_t sbase = smem_u32(dsm);
    proj_issue(sbase, 0, 0, i0, which, tid); cp_commit();
    proj_issue(sbase, 1, 1, i0, which, tid); cp_commit();

    float acc[16][4];
#pragma unroll
    for (int n8 = 0; n8 < 16; n8++)
#pragma unroll
        for (int q = 0; q < 4; q++) acc[n8][q] = 0.f;

    const int a_row = lane & 15;
    const int a_kh = lane >> 4;
    const int b_n = (lane & 7) | ((lane >> 1) & 8);
    const int b_kh = (lane >> 3) & 1;

#pragma unroll
    for (int kc = 0; kc < 4; kc++) {
        if (kc < 3) cp_wait1(); else cp_wait0();
        __syncthreads();

        const uint32_t stb = sbase + (uint32_t)((kc & 1) * PSTAGE_BYTES);
        const uint32_t sxh = stb + 0 * MAT_BYTES;
        const uint32_t sxl = stb + 1 * MAT_BYTES;
        const uint32_t swh = stb + 2 * MAT_BYTES;
        const uint32_t swl = stb + 3 * MAT_BYTES;

#pragma unroll
        for (int ks = 0; ks < 2; ks++) {
            const int k0 = ks * 16;
            const uint32_t a_off =
                (uint32_t)(((w * 16 + a_row) * SSTRIDE + k0 + a_kh * 8) * 2);
            const uint32_t b_off =
                (uint32_t)((b_n * SSTRIDE + k0 + b_kh * 8) * 2);

            uint32_t xh[4], xl[4], whr[8][4];
            ldsm4(xh, sxh + a_off);
            ldsm4(xl, sxl + a_off);

#pragma unroll
            for (int nt = 0; nt < 8; nt++) {
                ldsm4(whr[nt], swh + b_off + (uint32_t)(nt * 16 * SSTRIDE * 2));
                mma_f16(acc[2 * nt + 0], xh, &whr[nt][0]);
                mma_f16(acc[2 * nt + 1], xh, &whr[nt][2]);
            }
#pragma unroll
            for (int nt = 0; nt < 8; nt++) {
                mma_f16(acc[2 * nt + 0], xl, &whr[nt][0]);
                mma_f16(acc[2 * nt + 1], xl, &whr[nt][2]);
            }
#pragma unroll
            for (int nt = 0; nt < 8; nt++) {
                uint32_t wl[4];
                ldsm4(wl, swl + b_off + (uint32_t)(nt * 16 * SSTRIDE * 2));
                mma_f16(acc[2 * nt + 0], xh, &wl[0]);
                mma_f16(acc[2 * nt + 1], xh, &wl[2]);
            }
        }
        __syncthreads();
        if (kc < 2) { proj_issue(sbase, kc & 1, kc + 2, i0, which, tid); cp_commit(); }
    }

    const int cq = (lane & 3) * 2;
#pragma unroll
    for (int n8 = 0; n8 < 16; n8++) {
        const float b0 = b_s[n8 * 8 + cq];
        const float b1 = b_s[n8 * 8 + cq + 1];
        acc[n8][0] += b0; acc[n8][1] += b1;
        acc[n8][2] += b0; acc[n8][3] += b1;
    }

    float s0 = 0.f, s1 = 0.f;
#pragma unroll
    for (int n8 = 0; n8 < 16; n8++) {
        s0 += acc[n8][0] * acc[n8][0] + acc[n8][1] * acc[n8][1];
        s1 += acc[n8][2] * acc[n8][2] + acc[n8][3] * acc[n8][3];
    }
    s0 += __shfl_xor_sync(0xffffffffu, s0, 1);
    s0 += __shfl_xor_sync(0xffffffffu, s0, 2);
    s1 += __shfl_xor_sync(0xffffffffu, s1, 1);
    s1 += __shfl_xor_sync(0xffffffffu, s1, 2);

    const float invD = 1.0f / (float)ND;
    const float fro0 = sqrtf(s0 * s0 * invD * invD + 2.0f * s0 * invD + (float)ND);
    const float fro1 = sqrtf(s1 * s1 * invD * invD + 2.0f * s1 * invD + (float)ND);
    const float inv0 = 1.0f / (sqrtf((s0 * s0 * invD + s0) / (fro0 + EPSF)) + EPSF);
    const float inv1 = 1.0f / (sqrtf((s1 * s1 * invD + s1) / (fro1 + EPSF)) + EPSF);

    const int r0 = i0 + w * 16 + (lane >> 2);
    const int r1 = r0 + 8;

    if ((lane & 3) == 0) {
        float* sq = which ? g_ksq : g_qsq;
        sq[r0] = s0 * inv0 * inv0;
        sq[r1] = s1 * inv1 * inv1;
    }

    __half* outH = which ? g_kn_hi : g_qn_hi;
#pragma unroll
    for (int n8 = 0; n8 < 16; n8++) {
        const int col = n8 * 8 + cq;
        *(uint32_t*)&outH[(size_t)r0 * ND + col] =
            pack_h2(__float2half(acc[n8][0] * inv0), __float2half(acc[n8][1] * inv0));
        *(uint32_t*)&outH[(size_t)r1 * ND + col] =
            pack_h2(__float2half(acc[n8][2] * inv1), __float2half(acc[n8][3] * inv1));
    }
}

// ---------------------------------------------------------------------------
// Kernel B (persistent): phase 1 = ticketed gram tiles (single-product fp16
// HMMA + approx exp epilogue -> out + psum); grid-wide sync; phase 2 =
// in-place row normalization (L2-hot reads via __ldcg).
// ---------------------------------------------------------------------------
#define STAGE_BYTES (2 * MAT_BYTES)
#define GRAM_SMEM (2 * STAGE_BYTES)   // 40960

__device__ __forceinline__ void issue_chunk(uint32_t sbase, int st, int kc,
                                            int i0, int j0, int tid)
{
    const uint32_t stb = sbase + (uint32_t)(st * STAGE_BYTES);
#pragma unroll
    for (int it = 0; it < 2; it++) {
        const int t = it * 256 + tid;
        const int row = t >> 2;
        const int seg = t & 3;
        const uint32_t soff = (uint32_t)(row * 80 + seg * 16);
        const size_t gi = (size_t)(i0 + row) * ND + kc * 32 + seg * 8;
        const size_t gj = (size_t)(j0 + row) * ND + kc * 32 + seg * 8;
        cp16(stb + 0 * MAT_BYTES + soff, &g_qn_hi[gi]);
        cp16(stb + 1 * MAT_BYTES + soff, &g_kn_hi[gj]);
    }
}

__global__ __launch_bounds__(256, 2) void gram_fused_kernel(
    float* __restrict__ out, const int ncta)
{
    extern __shared__ __align__(16) char dsm[];
    __shared__ float ks_s[128];
    __shared__ float qs_s[128];
    __shared__ unsigned s_tile;
    __shared__ float s_inv;

    const int tid = threadIdx.x;
    const int lane = tid & 31;
    const int w = tid >> 5;
    const int wm = w & 3;
    const int wn = w >> 2;
    const uint32_t sbase = smem_u32(dsm);

    const int a_row = lane & 15;
    const int a_kh = lane >> 4;
    const int b_n = (lane & 7) | ((lane >> 1) & 8);
    const int b_kh = (lane >> 3) & 1;

    // ---------------- Phase 1: ticketed gram tiles ----------------
    for (;;) {
        if (tid == 0) s_tile = atomicAdd(&g_tile_ctr, 1u);
        __syncthreads();
        const unsigned t = s_tile;
        if (t >= 1024u) break;
        const int jb = (int)(t & 31u);
        const int i0 = (int)(t >> 5) * 128;
        const int j0 = jb * 128;

        if (tid < 128) ks_s[tid] = g_ksq[j0 + tid];
        else           qs_s[tid - 128] = g_qsq[i0 + tid - 128];

        issue_chunk(sbase, 0, 0, i0, j0, tid); cp_commit();
        issue_chunk(sbase, 1, 1, i0, j0, tid); cp_commit();

        float acc[2][8][4];
#pragma unroll
        for (int mt = 0; mt < 2; mt++)
#pragma unroll
            for (int n8 = 0; n8 < 8; n8++)
#pragma unroll
                for (int q = 0; q < 4; q++) acc[mt][n8][q] = 0.f;

#pragma unroll
        for (int kc = 0; kc < 4; kc++) {
            if (kc < 3) cp_wait1(); else cp_wait0();
            __syncthreads();

            const uint32_t stb = sbase + (uint32_t)((kc & 1) * STAGE_BYTES);
            const uint32_t ashi = stb + 0 * MAT_BYTES;
            const uint32_t bshi = stb + 1 * MAT_BYTES;

#pragma unroll
            for (int ks = 0; ks < 2; ks++) {
                const int k0 = ks * 16;
                const uint32_t a_off =
                    (uint32_t)(((wm * 32 + a_row) * SSTRIDE + k0 + a_kh * 8) * 2);
                const uint32_t b_off0 =
                    (uint32_t)(((wn * 64 + b_n) * SSTRIDE + k0 + b_kh * 8) * 2);

                uint32_t ahi[2][4], bf[4][4];
#pragma unroll
                for (int mt = 0; mt < 2; mt++)
                    ldsm4(ahi[mt], ashi + a_off + (uint32_t)(mt * 16 * SSTRIDE * 2));
#pragma unroll
                for (int nt = 0; nt < 4; nt++)
                    ldsm4(bf[nt], bshi + b_off0 + (uint32_t)(nt * 16 * SSTRIDE * 2));

#pragma unroll
                for (int mt = 0; mt < 2; mt++)
#pragma unroll
                    for (int nt = 0; nt < 4; nt++) {
                        mma_f16(acc[mt][nt * 2 + 0], ahi[mt], &bf[nt][0]);
                        mma_f16(acc[mt][nt * 2 + 1], ahi[mt], &bf[nt][2]);
                    }
            }
            __syncthreads();
            if (kc < 2) { issue_chunk(sbase, kc & 1, kc + 2, i0, j0, tid); cp_commit(); }
        }

        // Epilogue + partial row sums (approx math).
        const int rq = lane >> 2;
        const int cq = (lane & 3) * 2;
        float rs[2][2];
        rs[0][0] = rs[0][1] = rs[1][0] = rs[1][1] = 0.f;

#pragma unroll
        for (int mt = 0; mt < 2; mt++) {
            const int rl0 = wm * 32 + mt * 16 + rq;
            const float qs0 = qs_s[rl0];
            const float qs1 = qs_s[rl0 + 8];
#pragma unroll
            for (int n8 = 0; n8 < 8; n8++) {
                const int cl = wn * 64 + n8 * 8 + cq;
                const float k0v = ks_s[cl], k1v = ks_s[cl + 1];
                const float* a = acc[mt][n8];

                float d00 = fmaxf(qs0 + k0v - 2.0f * a[0], 0.0f);
                float d01 = fmaxf(qs0 + k1v - 2.0f * a[1], 0.0f);
                float d10 = fmaxf(qs1 + k0v - 2.0f * a[2], 0.0f);
                float d11 = fmaxf(qs1 + k1v - 2.0f * a[3], 0.0f);

                float2 e0, e1;
                e0.x = __expf(__fdividef(TEMPF, 1.0f + fsqrt_ap(d00)));
                e0.y = __expf(__fdividef(TEMPF, 1.0f + fsqrt_ap(d01)));
                e1.x = __expf(__fdividef(TEMPF, 1.0f + fsqrt_ap(d10)));
                e1.y = __expf(__fdividef(TEMPF, 1.0f + fsqrt_ap(d11)));

                rs[mt][0] += e0.x + e0.y;
                rs[mt][1] += e1.x + e1.y;

                *(float2*)&out[(size_t)(i0 + rl0) * NB + j0 + cl] = e0;
                *(float2*)&out[(size_t)(i0 + rl0 + 8) * NB + j0 + cl] = e1;
            }
        }

#pragma unroll
        for (int mt = 0; mt < 2; mt++)
#pragma unroll
            for (int h = 0; h < 2; h++) {
                float s = rs[mt][h];
                s += __shfl_xor_sync(0xffffffffu, s, 1);
                s += __shfl_xor_sync(0xffffffffu, s, 2);
                if ((lane & 3) == 0) {
                    const int row = i0 + wm * 32 + mt * 16 + rq + h * 8;
                    g_psum[(size_t)row * 64 + jb * 2 + wn] = s;
                }
            }
        __syncthreads();   // protect ks_s/qs_s reuse next iteration
    }

    // ---------------- Grid-wide sync ----------------
    __threadfence();
    __syncthreads();
    if (tid == 0) {
        atomicAdd(&g_done_ctr, 1u);
        while (*((volatile unsigned*)&g_done_ctr) < (unsigned)ncta)
            __nanosleep(64);
    }
    __syncthreads();
    __threadfence();

    // ---------------- Phase 2: row normalization ----------------
    for (int row = blockIdx.x; row < NB; row += ncta) {
        if (tid < 32) {
            float s = __ldcg(&g_psum[(size_t)row * 64 + tid]) +
                      __ldcg(&g_psum[(size_t)row * 64 + 32 + tid]);
#pragma unroll
            for (int o = 16; o > 0; o >>= 1)
                s += __shfl_xor_sync(0xffffffffu, s, o);
            if (tid == 0) s_inv = 1.0f / s;
        }
        __syncthreads();
        const float inv = s_inv;

        float4* p = (float4*)(out + (size_t)row * NB);
        float4 v[4];
#pragma unroll
        for (int q = 0; q < 4; q++) v[q] = __ldcg(&p[tid + q * 256]);
#pragma unroll
        for (int q = 0; q < 4; q++) {
            v[q].x *= inv; v[q].y *= inv; v[q].z *= inv; v[q].w *= inv;
            p[tid + q * 256] = v[q];
        }
        __syncthreads();   // protect s_inv reuse
    }
}

// ---------------------------------------------------------------------------
// Launch
// ---------------------------------------------------------------------------
extern "C" void kernel_launch(void* const* d_in, const int* in_sizes, int n_in,
                              void* d_out, int out_size)
{
    (void)in_sizes; (void)n_in; (void)out_size;
    const float* qp = (const float*)d_in[0];
    const float* kp = (const float*)d_in[1];
    const float* Wq = (const float*)d_in[2];
    const float* bq = (const float*)d_in[3];
    const float* Wk = (const float*)d_in[4];
    const float* bk = (const float*)d_in[5];
    float* out = (float*)d_out;

    int sms = 0;
    cudaDeviceGetAttribute(&sms, cudaDevAttrMultiProcessorCount, 0);
    const int ncta = 2 * sms;   // __launch_bounds__(256,2) guarantees co-residency

    cudaFuncSetAttribute(proj_mma_kernel,
                         cudaFuncAttributeMaxDynamicSharedMemorySize, PROJ_SMEM);
    cudaFuncSetAttribute(gram_fused_kernel,
                         cudaFuncAttributeMaxDynamicSharedMemorySize, GRAM_SMEM);

    split_kernel<<<1056, 256>>>(qp, kp, Wq, Wk);

    dim3 gp(NB / 128, 2);
    proj_mma_kernel<<<gp, 256, PROJ_SMEM>>>(bq, bk);

    gram_fused_kernel<<<ncta, 256, GRAM_SMEM>>>(out, ncta);
}

// round 13
// speedup vs baseline: 1.1338x; 1.1338x over previous
#include <cuda_runtime.h>
#include <cuda_fp16.h>
#include <math.h>
#include <stdint.h>

// Problem constants
#define NB 4096
#define ND 128
#define EPSF 1e-8f
#define TEMPF 11.313708498984761f   // sqrt(128)

// Scratch (device globals; no allocation allowed)
__device__ __half g_qn_hi[NB * ND];
__device__ __half g_kn_hi[NB * ND];
__device__ float g_qsq[NB];
__device__ float g_ksq[NB];
__device__ float g_psum[NB * 64];   // per-(row, jblock-half) partial row sums

// ---------------------------------------------------------------------------
// PTX helpers (base compute_103 — NO sm_103a-only instructions)
// ---------------------------------------------------------------------------
__device__ __forceinline__ uint32_t smem_u32(const void* p) {
    uint32_t a;
    asm("{ .reg .u64 t; cvta.to.shared.u64 t, %1; cvt.u32.u64 %0, t; }"
        : "=r"(a) : "l"(p));
    return a;
}

__device__ __forceinline__ void ldsm4(uint32_t* r, uint32_t addr) {
    asm volatile("ldmatrix.sync.aligned.m8n8.x4.shared.b16 {%0,%1,%2,%3}, [%4];"
                 : "=r"(r[0]), "=r"(r[1]), "=r"(r[2]), "=r"(r[3]) : "r"(addr));
}

__device__ __forceinline__ void mma_f16(float* c, const uint32_t* a,
                                        const uint32_t* b) {
    asm volatile(
        "mma.sync.aligned.m16n8k16.row.col.f32.f16.f16.f32 "
        "{%0,%1,%2,%3}, {%4,%5,%6,%7}, {%8,%9}, {%0,%1,%2,%3};"
        : "+f"(c[0]), "+f"(c[1]), "+f"(c[2]), "+f"(c[3])
        : "r"(a[0]), "r"(a[1]), "r"(a[2]), "r"(a[3]), "r"(b[0]), "r"(b[1]));
}

__device__ __forceinline__ void cp16(uint32_t s, const void* g) {
    asm volatile("cp.async.cg.shared.global [%0], [%1], 16;" :: "r"(s), "l"(g));
}
__device__ __forceinline__ void cp_commit() {
    asm volatile("cp.async.commit_group;" ::: "memory");
}
__device__ __forceinline__ void cp_wait1() {
    asm volatile("cp.async.wait_group 1;" ::: "memory");
}
__device__ __forceinline__ void cp_wait0() {
    asm volatile("cp.async.wait_group 0;" ::: "memory");
}

__device__ __forceinline__ uint32_t pack_h2(__half a, __half b) {
    __half2 t(a, b);
    return *reinterpret_cast<uint32_t*>(&t);
}

// fast approx sqrt (1 MUFU op; ~2^-21 rel err; sqrt.approx(0)=0)
__device__ __forceinline__ float fsqrt_ap(float x) {
    float r;
    asm("sqrt.approx.f32 %0, %1;" : "=f"(r) : "f"(x));
    return r;
}

// ---------------------------------------------------------------------------
// Shared tile-layout constants
// ---------------------------------------------------------------------------
#define SSTRIDE 40                 // fp16 elems per smem row (80 B)
#define MAT_BYTES 10240            // 128 rows * 80 B

// ---------------------------------------------------------------------------
// Kernel A: projection via compensated HMMA + analytic metric normalization.
// fp32 X/W loaded directly; hi/lo fp16 split done in-register, staged to
// padded smem, consumed by the validated ldmatrix/HMMA path.
// q = Xhi*Whi + Xlo*Whi + Xhi*Wlo (+bias); emits fp16 hi only + sq norms.
// ---------------------------------------------------------------------------
__global__ __launch_bounds__(256) void proj_mma_kernel(
    const float* __restrict__ Xq, const float* __restrict__ Wq,
    const float* __restrict__ bq,
    const float* __restrict__ Xk, const float* __restrict__ Wk,
    const float* __restrict__ bk)
{
    __shared__ __align__(16) __half sxh[128][SSTRIDE];
    __shared__ __align__(16) __half sxl[128][SSTRIDE];
    __shared__ __align__(16) __half swh[128][SSTRIDE];
    __shared__ __align__(16) __half swl[128][SSTRIDE];
    __shared__ float b_s[128];

    const int tid = threadIdx.x;
    const int lane = tid & 31;
    const int w = tid >> 5;
    const int which = blockIdx.y;
    const int i0 = blockIdx.x * 128;

    const float* X = which ? Xk : Xq;
    const float* W = which ? Wk : Wq;
    if (tid < 128) b_s[tid] = which ? bk[tid] : bq[tid];

    const uint32_t a_sxh = smem_u32(sxh);
    const uint32_t a_sxl = smem_u32(sxl);
    const uint32_t a_swh = smem_u32(swh);
    const uint32_t a_swl = smem_u32(swl);

    float acc[16][4];
#pragma unroll
    for (int n8 = 0; n8 < 16; n8++)
#pragma unroll
        for (int q = 0; q < 4; q++) acc[n8][q] = 0.f;

    const int a_row = lane & 15;
    const int a_kh = lane >> 4;
    const int b_n = (lane & 7) | ((lane >> 1) & 8);
    const int b_kh = (lane >> 3) & 1;

    for (int kc = 0; kc < 4; kc++) {
        // Load fp32 chunk (128 x 32 of X and W), split to hi/lo, stage in smem.
#pragma unroll
        for (int it = 0; it < 4; it++) {
            const int idx = it * 256 + tid;      // 0..1023 float4 slots
            const int row = idx >> 3;            // 8 float4 per row (32 floats)
            const int c4 = idx & 7;
            const float4 xv = *(const float4*)&X[(size_t)(i0 + row) * ND + kc * 32 + c4 * 4];
            const float4 wv = *(const float4*)&W[(size_t)row * ND + kc * 32 + c4 * 4];

            {
                const __half h0 = __float2half(xv.x), h1 = __float2half(xv.y);
                const __half h2 = __float2half(xv.z), h3 = __float2half(xv.w);
                const __half l0 = __float2half(xv.x - __half2float(h0));
                const __half l1 = __float2half(xv.y - __half2float(h1));
                const __half l2 = __float2half(xv.z - __half2float(h2));
                const __half l3 = __float2half(xv.w - __half2float(h3));
                *(uint2*)&sxh[row][c4 * 4] = make_uint2(pack_h2(h0, h1), pack_h2(h2, h3));
                *(uint2*)&sxl[row][c4 * 4] = make_uint2(pack_h2(l0, l1), pack_h2(l2, l3));
            }
            {
                const __half h0 = __float2half(wv.x), h1 = __float2half(wv.y);
                const __half h2 = __float2half(wv.z), h3 = __float2half(wv.w);
                const __half l0 = __float2half(wv.x - __half2float(h0));
                const __half l1 = __float2half(wv.y - __half2float(h1));
                const __half l2 = __float2half(wv.z - __half2float(h2));
                const __half l3 = __float2half(wv.w - __half2float(h3));
                *(uint2*)&swh[row][c4 * 4] = make_uint2(pack_h2(h0, h1), pack_h2(h2, h3));
                *(uint2*)&swl[row][c4 * 4] = make_uint2(pack_h2(l0, l1), pack_h2(l2, l3));
            }
        }
        __syncthreads();

#pragma unroll
        for (int ks = 0; ks < 2; ks++) {
            const int k0 = ks * 16;
            const uint32_t a_off =
                (uint32_t)(((w * 16 + a_row) * SSTRIDE + k0 + a_kh * 8) * 2);
            const uint32_t b_off =
                (uint32_t)((b_n * SSTRIDE + k0 + b_kh * 8) * 2);

            uint32_t xh[4], xl[4], whr[8][4];
            ldsm4(xh, a_sxh + a_off);
            ldsm4(xl, a_sxl + a_off);

#pragma unroll
            for (int nt = 0; nt < 8; nt++) {
                ldsm4(whr[nt], a_swh + b_off + (uint32_t)(nt * 16 * SSTRIDE * 2));
                mma_f16(acc[2 * nt + 0], xh, &whr[nt][0]);
                mma_f16(acc[2 * nt + 1], xh, &whr[nt][2]);
            }
#pragma unroll
            for (int nt = 0; nt < 8; nt++) {
                mma_f16(acc[2 * nt + 0], xl, &whr[nt][0]);
                mma_f16(acc[2 * nt + 1], xl, &whr[nt][2]);
            }
#pragma unroll
            for (int nt = 0; nt < 8; nt++) {
                uint32_t wl[4];
                ldsm4(wl, a_swl + b_off + (uint32_t)(nt * 16 * SSTRIDE * 2));
                mma_f16(acc[2 * nt + 0], xh, &wl[0]);
                mma_f16(acc[2 * nt + 1], xh, &wl[2]);
            }
        }
        __syncthreads();
    }

    const int cq = (lane & 3) * 2;
#pragma unroll
    for (int n8 = 0; n8 < 16; n8++) {
        const float b0 = b_s[n8 * 8 + cq];
        const float b1 = b_s[n8 * 8 + cq + 1];
        acc[n8][0] += b0; acc[n8][1] += b1;
        acc[n8][2] += b0; acc[n8][3] += b1;
    }

    float s0 = 0.f, s1 = 0.f;
#pragma unroll
    for (int n8 = 0; n8 < 16; n8++) {
        s0 += acc[n8][0] * acc[n8][0] + acc[n8][1] * acc[n8][1];
        s1 += acc[n8][2] * acc[n8][2] + acc[n8][3] * acc[n8][3];
    }
    s0 += __shfl_xor_sync(0xffffffffu, s0, 1);
    s0 += __shfl_xor_sync(0xffffffffu, s0, 2);
    s1 += __shfl_xor_sync(0xffffffffu, s1, 1);
    s1 += __shfl_xor_sync(0xffffffffu, s1, 2);

    const float invD = 1.0f / (float)ND;
    const float fro0 = sqrtf(s0 * s0 * invD * invD + 2.0f * s0 * invD + (float)ND);
    const float fro1 = sqrtf(s1 * s1 * invD * invD + 2.0f * s1 * invD + (float)ND);
    const float inv0 = 1.0f / (sqrtf((s0 * s0 * invD + s0) / (fro0 + EPSF)) + EPSF);
    const float inv1 = 1.0f / (sqrtf((s1 * s1 * invD + s1) / (fro1 + EPSF)) + EPSF);

    const int r0 = i0 + w * 16 + (lane >> 2);
    const int r1 = r0 + 8;

    if ((lane & 3) == 0) {
        float* sq = which ? g_ksq : g_qsq;
        sq[r0] = s0 * inv0 * inv0;
        sq[r1] = s1 * inv1 * inv1;
    }

    __half* outH = which ? g_kn_hi : g_qn_hi;
#pragma unroll
    for (int n8 = 0; n8 < 16; n8++) {
        const int col = n8 * 8 + cq;
        *(uint32_t*)&outH[(size_t)r0 * ND + col] =
            pack_h2(__float2half(acc[n8][0] * inv0), __float2half(acc[n8][1] * inv0));
        *(uint32_t*)&outH[(size_t)r1 * ND + col] =
            pack_h2(__float2half(acc[n8][2] * inv1), __float2half(acc[n8][3] * inv1));
    }
}

// ---------------------------------------------------------------------------
// Kernel B: single-product fp16 HMMA Gram + fused exp-logit epilogue
// (approx sqrt/div) + per-warp partial row sums into g_psum.
// Stage = 2 matrices (qn_hi, kn_hi). CTA 128x128, 8 warps (4M x 2N).
// ---------------------------------------------------------------------------
#define STAGE_BYTES (2 * MAT_BYTES)
#define GRAM_SMEM (2 * STAGE_BYTES)   // 40960

__device__ __forceinline__ void issue_chunk(uint32_t sbase, int st, int kc,
                                            int i0, int j0, int tid)
{
    const uint32_t stb = sbase + (uint32_t)(st * STAGE_BYTES);
#pragma unroll
    for (int it = 0; it < 2; it++) {
        const int t = it * 256 + tid;
        const int row = t >> 2;
        const int seg = t & 3;
        const uint32_t soff = (uint32_t)(row * 80 + seg * 16);
        const size_t gi = (size_t)(i0 + row) * ND + kc * 32 + seg * 8;
        const size_t gj = (size_t)(j0 + row) * ND + kc * 32 + seg * 8;
        cp16(stb + 0 * MAT_BYTES + soff, &g_qn_hi[gi]);
        cp16(stb + 1 * MAT_BYTES + soff, &g_kn_hi[gj]);
    }
}

__global__ __launch_bounds__(256, 2) void gram_exp_kernel(float* __restrict__ out)
{
    extern __shared__ __align__(16) char dsm[];
    __shared__ float ks_s[128];
    __shared__ float qs_s[128];

    const int tid = threadIdx.x;
    const int lane = tid & 31;
    const int w = tid >> 5;
    const int wm = w & 3;
    const int wn = w >> 2;
    const int i0 = blockIdx.y * 128;
    const int j0 = blockIdx.x * 128;

    if (tid < 128) ks_s[tid] = g_ksq[j0 + tid];
    else           qs_s[tid - 128] = g_qsq[i0 + tid - 128];

    const uint32_t sbase = smem_u32(dsm);

    issue_chunk(sbase, 0, 0, i0, j0, tid); cp_commit();
    issue_chunk(sbase, 1, 1, i0, j0, tid); cp_commit();

    float acc[2][8][4];
#pragma unroll
    for (int mt = 0; mt < 2; mt++)
#pragma unroll
        for (int n8 = 0; n8 < 8; n8++)
#pragma unroll
            for (int q = 0; q < 4; q++) acc[mt][n8][q] = 0.f;

    const int a_row = lane & 15;
    const int a_kh = lane >> 4;
    const int b_n = (lane & 7) | ((lane >> 1) & 8);
    const int b_kh = (lane >> 3) & 1;

#pragma unroll
    for (int kc = 0; kc < 4; kc++) {
        if (kc < 3) cp_wait1(); else cp_wait0();
        __syncthreads();

        const uint32_t stb = sbase + (uint32_t)((kc & 1) * STAGE_BYTES);
        const uint32_t ashi = stb + 0 * MAT_BYTES;
        const uint32_t bshi = stb + 1 * MAT_BYTES;

#pragma unroll
        for (int ks = 0; ks < 2; ks++) {
            const int k0 = ks * 16;
            const uint32_t a_off =
                (uint32_t)(((wm * 32 + a_row) * SSTRIDE + k0 + a_kh * 8) * 2);
            const uint32_t b_off0 =
                (uint32_t)(((wn * 64 + b_n) * SSTRIDE + k0 + b_kh * 8) * 2);

            uint32_t ahi[2][4], bf[4][4];
#pragma unroll
            for (int mt = 0; mt < 2; mt++)
                ldsm4(ahi[mt], ashi + a_off + (uint32_t)(mt * 16 * SSTRIDE * 2));
#pragma unroll
            for (int nt = 0; nt < 4; nt++)
                ldsm4(bf[nt], bshi + b_off0 + (uint32_t)(nt * 16 * SSTRIDE * 2));

#pragma unroll
            for (int mt = 0; mt < 2; mt++)
#pragma unroll
                for (int nt = 0; nt < 4; nt++) {
                    mma_f16(acc[mt][nt * 2 + 0], ahi[mt], &bf[nt][0]);
                    mma_f16(acc[mt][nt * 2 + 1], ahi[mt], &bf[nt][2]);
                }
        }
        __syncthreads();
        if (kc < 2) { issue_chunk(sbase, kc & 1, kc + 2, i0, j0, tid); cp_commit(); }
    }

    // Epilogue + partial row sums (approx math).
    const int rq = lane >> 2;
    const int cq = (lane & 3) * 2;
    float rs[2][2];
    rs[0][0] = rs[0][1] = rs[1][0] = rs[1][1] = 0.f;

#pragma unroll
    for (int mt = 0; mt < 2; mt++) {
        const int rl0 = wm * 32 + mt * 16 + rq;
        const float qs0 = qs_s[rl0];
        const float qs1 = qs_s[rl0 + 8];
#pragma unroll
        for (int n8 = 0; n8 < 8; n8++) {
            const int cl = wn * 64 + n8 * 8 + cq;
            const float k0v = ks_s[cl], k1v = ks_s[cl + 1];
            const float* a = acc[mt][n8];

            float d00 = fmaxf(qs0 + k0v - 2.0f * a[0], 0.0f);
            float d01 = fmaxf(qs0 + k1v - 2.0f * a[1], 0.0f);
            float d10 = fmaxf(qs1 + k0v - 2.0f * a[2], 0.0f);
            float d11 = fmaxf(qs1 + k1v - 2.0f * a[3], 0.0f);

            float2 e0, e1;
            e0.x = __expf(__fdividef(TEMPF, 1.0f + fsqrt_ap(d00)));
            e0.y = __expf(__fdividef(TEMPF, 1.0f + fsqrt_ap(d01)));
            e1.x = __expf(__fdividef(TEMPF, 1.0f + fsqrt_ap(d10)));
            e1.y = __expf(__fdividef(TEMPF, 1.0f + fsqrt_ap(d11)));

            rs[mt][0] += e0.x + e0.y;
            rs[mt][1] += e1.x + e1.y;

            *(float2*)&out[(size_t)(i0 + rl0) * NB + j0 + cl] = e0;
            *(float2*)&out[(size_t)(i0 + rl0 + 8) * NB + j0 + cl] = e1;
        }
    }

    // Reduce partial sums over the 4 lanes sharing a row; store to g_psum.
#pragma unroll
    for (int mt = 0; mt < 2; mt++)
#pragma unroll
        for (int h = 0; h < 2; h++) {
            float s = rs[mt][h];
            s += __shfl_xor_sync(0xffffffffu, s, 1);
            s += __shfl_xor_sync(0xffffffffu, s, 2);
            if ((lane & 3) == 0) {
                const int row = i0 + wm * 32 + mt * 16 + rq + h * 8;
                g_psum[(size_t)row * 64 + blockIdx.x * 2 + wn] = s;
            }
        }
}

// ---------------------------------------------------------------------------
// Kernel C: normalize rows using precomputed partial sums. 512 thr / 2 rows.
// ---------------------------------------------------------------------------
__global__ __launch_bounds__(512) void scale_kernel(float* __restrict__ out)
{
    __shared__ float sinv[2];
    const int tid = threadIdx.x;
    const int half = tid >> 8;
    const int t = tid & 255;
    const int row = blockIdx.x * 2 + half;

    float4* p = (float4*)(out + (size_t)row * NB);
    float4 v[4];
#pragma unroll
    for (int q = 0; q < 4; q++) v[q] = p[t + q * 256];

    if (t < 32) {
        float s = g_psum[(size_t)row * 64 + t] + g_psum[(size_t)row * 64 + 32 + t];
#pragma unroll
        for (int o = 16; o > 0; o >>= 1) s += __shfl_xor_sync(0xffffffffu, s, o);
        if (t == 0) sinv[half] = 1.0f / s;
    }
    __syncthreads();
    const float inv = sinv[half];

#pragma unroll
    for (int q = 0; q < 4; q++) {
        v[q].x *= inv; v[q].y *= inv; v[q].z *= inv; v[q].w *= inv;
        p[t + q * 256] = v[q];
    }
}

// ---------------------------------------------------------------------------
// Launch
// ---------------------------------------------------------------------------
extern "C" void kernel_launch(void* const* d_in, const int* in_sizes, int n_in,
                              void* d_out, int out_size)
{
    (void)in_sizes; (void)n_in; (void)out_size;
    const float* qp = (const float*)d_in[0];
    const float* kp = (const float*)d_in[1];
    const float* Wq = (const float*)d_in[2];
    const float* bq = (const float*)d_in[3];
    const float* Wk = (const float*)d_in[4];
    const float* bk = (const float*)d_in[5];
    float* out = (float*)d_out;

    cudaFuncSetAttribute(gram_exp_kernel,
                         cudaFuncAttributeMaxDynamicSharedMemorySize, GRAM_SMEM);

    dim3 gp(NB / 128, 2);
    proj_mma_kernel<<<gp, 256>>>(qp, Wq, bq, kp, Wk, bk);

    dim3 g(NB / 128, NB / 128);
    gram_exp_kernel<<<g, 256, GRAM_SMEM>>>(out);

    scale_kernel<<<NB / 2, 512>>>(out);
}

// round 14
// speedup vs baseline: 1.1863x; 1.0463x over previous
#include <cuda_runtime.h>
#include <cuda_fp16.h>
#include <math.h>
#include <stdint.h>

// Problem constants
#define NB 4096
#define ND 128
#define EPSF 1e-8f
#define TEMPF 11.313708498984761f   // sqrt(128)

// Scratch (device globals; no allocation allowed)
__device__ __half g_qn_hi[NB * ND];
__device__ __half g_kn_hi[NB * ND];
__device__ float g_qsq[NB];
__device__ float g_ksq[NB];
__device__ float g_psum[NB * 64];   // per-(row, jblock-half) partial row sums

// ---------------------------------------------------------------------------
// PTX helpers (base compute_103 — NO sm_103a-only instructions)
// ---------------------------------------------------------------------------
__device__ __forceinline__ uint32_t smem_u32(const void* p) {
    uint32_t a;
    asm("{ .reg .u64 t; cvta.to.shared.u64 t, %1; cvt.u32.u64 %0, t; }"
        : "=r"(a) : "l"(p));
    return a;
}

__device__ __forceinline__ void ldsm4(uint32_t* r, uint32_t addr) {
    asm volatile("ldmatrix.sync.aligned.m8n8.x4.shared.b16 {%0,%1,%2,%3}, [%4];"
                 : "=r"(r[0]), "=r"(r[1]), "=r"(r[2]), "=r"(r[3]) : "r"(addr));
}

__device__ __forceinline__ void mma_f16(float* c, const uint32_t* a,
                                        const uint32_t* b) {
    asm volatile(
        "mma.sync.aligned.m16n8k16.row.col.f32.f16.f16.f32 "
        "{%0,%1,%2,%3}, {%4,%5,%6,%7}, {%8,%9}, {%0,%1,%2,%3};"
        : "+f"(c[0]), "+f"(c[1]), "+f"(c[2]), "+f"(c[3])
        : "r"(a[0]), "r"(a[1]), "r"(a[2]), "r"(a[3]), "r"(b[0]), "r"(b[1]));
}

__device__ __forceinline__ void cp16(uint32_t s, const void* g) {
    asm volatile("cp.async.cg.shared.global [%0], [%1], 16;" :: "r"(s), "l"(g));
}
__device__ __forceinline__ void cp_commit() {
    asm volatile("cp.async.commit_group;" ::: "memory");
}
__device__ __forceinline__ void cp_wait1() {
    asm volatile("cp.async.wait_group 1;" ::: "memory");
}
__device__ __forceinline__ void cp_wait0() {
    asm volatile("cp.async.wait_group 0;" ::: "memory");
}

__device__ __forceinline__ uint32_t pack_h2(__half a, __half b) {
    __half2 t(a, b);
    return *reinterpret_cast<uint32_t*>(&t);
}

// fast approx sqrt (1 MUFU op; ~2^-21 rel err; sqrt.approx(0)=0)
__device__ __forceinline__ float fsqrt_ap(float x) {
    float r;
    asm("sqrt.approx.f32 %0, %1;" : "=f"(r) : "f"(x));
    return r;
}

// ---------------------------------------------------------------------------
// Shared tile-layout constants
// ---------------------------------------------------------------------------
#define SSTRIDE 40                 // fp16 elems per smem row (80 B)
#define MAT_BYTES 10240            // 128 rows * 80 B

// ---------------------------------------------------------------------------
// Kernel A: projection via compensated HMMA + analytic metric normalization.
// 64-row tiles, grid (64,2) = 128 CTAs; warps 4(M) x 2(N), warp tile 16x64.
// Register double-buffered prefetch hides global-load latency.
// q = Xhi*Whi + Xlo*Whi + Xhi*Wlo (+bias); emits fp16 hi only + sq norms.
// ---------------------------------------------------------------------------
#define PROWS 64

__global__ __launch_bounds__(256) void proj_mma_kernel(
    const float* __restrict__ Xq, const float* __restrict__ Wq,
    const float* __restrict__ bq,
    const float* __restrict__ Xk, const float* __restrict__ Wk,
    const float* __restrict__ bk)
{
    __shared__ __align__(16) __half sxh[PROWS][SSTRIDE];
    __shared__ __align__(16) __half sxl[PROWS][SSTRIDE];
    __shared__ __align__(16) __half swh[128][SSTRIDE];
    __shared__ __align__(16) __half swl[128][SSTRIDE];
    __shared__ float b_s[128];
    __shared__ float red[PROWS][2];

    const int tid = threadIdx.x;
    const int lane = tid & 31;
    const int w = tid >> 5;
    const int wm = w & 3;          // M quarter (16 rows)
    const int wn = w >> 2;         // N half (64 cols)
    const int which = blockIdx.y;
    const int i0 = blockIdx.x * PROWS;

    const float* X = which ? Xk : Xq;
    const float* W = which ? Wk : Wq;
    if (tid < 128) b_s[tid] = which ? bk[tid] : bq[tid];

    const uint32_t a_sxh = smem_u32(sxh);
    const uint32_t a_sxl = smem_u32(sxl);
    const uint32_t a_swh = smem_u32(swh);
    const uint32_t a_swl = smem_u32(swl);

    // per-thread load slots: X 2 float4 (64 rows x 8 f4), W 4 float4 (128 x 8)
    const int xrow0 = tid >> 3;            // slot it=0: rows 0..31
    const int xc4 = tid & 7;
    // slot it: row = it*32 + xrow0

    float4 xcur[2], wcur[4], xnxt[2], wnxt[4];

#pragma unroll
    for (int it = 0; it < 2; it++)
        xcur[it] = *(const float4*)&X[(size_t)(i0 + it * 32 + xrow0) * ND + 0 * 32 + xc4 * 4];
#pragma unroll
    for (int it = 0; it < 4; it++)
        wcur[it] = *(const float4*)&W[(size_t)(it * 32 + xrow0) * ND + 0 * 32 + xc4 * 4];

    float acc[8][4];
#pragma unroll
    for (int n8 = 0; n8 < 8; n8++)
#pragma unroll
        for (int q = 0; q < 4; q++) acc[n8][q] = 0.f;

    const int a_row = lane & 15;
    const int a_kh = lane >> 4;
    const int b_n = (lane & 7) | ((lane >> 1) & 8);
    const int b_kh = (lane >> 3) & 1;

    for (int kc = 0; kc < 4; kc++) {
        // prefetch next chunk (issues before current conversion stalls)
        if (kc < 3) {
#pragma unroll
            for (int it = 0; it < 2; it++)
                xnxt[it] = *(const float4*)&X[(size_t)(i0 + it * 32 + xrow0) * ND + (kc + 1) * 32 + xc4 * 4];
#pragma unroll
            for (int it = 0; it < 4; it++)
                wnxt[it] = *(const float4*)&W[(size_t)(it * 32 + xrow0) * ND + (kc + 1) * 32 + xc4 * 4];
        }

        // convert current chunk into smem
#pragma unroll
        for (int it = 0; it < 2; it++) {
            const int row = it * 32 + xrow0;
            const float4 v = xcur[it];
            const __half h0 = __float2half(v.x), h1 = __float2half(v.y);
            const __half h2 = __float2half(v.z), h3 = __float2half(v.w);
            const __half l0 = __float2half(v.x - __half2float(h0));
            const __half l1 = __float2half(v.y - __half2float(h1));
            const __half l2 = __float2half(v.z - __half2float(h2));
            const __half l3 = __float2half(v.w - __half2float(h3));
            *(uint2*)&sxh[row][xc4 * 4] = make_uint2(pack_h2(h0, h1), pack_h2(h2, h3));
            *(uint2*)&sxl[row][xc4 * 4] = make_uint2(pack_h2(l0, l1), pack_h2(l2, l3));
        }
#pragma unroll
        for (int it = 0; it < 4; it++) {
            const int row = it * 32 + xrow0;
            const float4 v = wcur[it];
            const __half h0 = __float2half(v.x), h1 = __float2half(v.y);
            const __half h2 = __float2half(v.z), h3 = __float2half(v.w);
            const __half l0 = __float2half(v.x - __half2float(h0));
            const __half l1 = __float2half(v.y - __half2float(h1));
            const __half l2 = __float2half(v.z - __half2float(h2));
            const __half l3 = __float2half(v.w - __half2float(h3));
            *(uint2*)&swh[row][xc4 * 4] = make_uint2(pack_h2(h0, h1), pack_h2(h2, h3));
            *(uint2*)&swl[row][xc4 * 4] = make_uint2(pack_h2(l0, l1), pack_h2(l2, l3));
        }
        __syncthreads();

#pragma unroll
        for (int ks = 0; ks < 2; ks++) {
            const int k0 = ks * 16;
            const uint32_t a_off =
                (uint32_t)(((wm * 16 + a_row) * SSTRIDE + k0 + a_kh * 8) * 2);
            const uint32_t b_off =
                (uint32_t)(((wn * 64 + b_n) * SSTRIDE + k0 + b_kh * 8) * 2);

            uint32_t xh[4], xl[4], whr[4][4];
            ldsm4(xh, a_sxh + a_off);
            ldsm4(xl, a_sxl + a_off);

#pragma unroll
            for (int nt = 0; nt < 4; nt++) {
                ldsm4(whr[nt], a_swh + b_off + (uint32_t)(nt * 16 * SSTRIDE * 2));
                mma_f16(acc[2 * nt + 0], xh, &whr[nt][0]);
                mma_f16(acc[2 * nt + 1], xh, &whr[nt][2]);
            }
#pragma unroll
            for (int nt = 0; nt < 4; nt++) {
                mma_f16(acc[2 * nt + 0], xl, &whr[nt][0]);
                mma_f16(acc[2 * nt + 1], xl, &whr[nt][2]);
            }
#pragma unroll
            for (int nt = 0; nt < 4; nt++) {
                uint32_t wl[4];
                ldsm4(wl, a_swl + b_off + (uint32_t)(nt * 16 * SSTRIDE * 2));
                mma_f16(acc[2 * nt + 0], xh, &wl[0]);
                mma_f16(acc[2 * nt + 1], xh, &wl[2]);
            }
        }
        __syncthreads();

#pragma unroll
        for (int it = 0; it < 2; it++) xcur[it] = xnxt[it];
#pragma unroll
        for (int it = 0; it < 4; it++) wcur[it] = wnxt[it];
    }

    // bias add (warp covers cols wn*64 + n8*8 + cq)
    const int cq = (lane & 3) * 2;
#pragma unroll
    for (int n8 = 0; n8 < 8; n8++) {
        const int cl = wn * 64 + n8 * 8 + cq;
        acc[n8][0] += b_s[cl];     acc[n8][1] += b_s[cl + 1];
        acc[n8][2] += b_s[cl];     acc[n8][3] += b_s[cl + 1];
    }

    // per-warp (64-col) partial row sums of squares
    float s0 = 0.f, s1 = 0.f;
#pragma unroll
    for (int n8 = 0; n8 < 8; n8++) {
        s0 += acc[n8][0] * acc[n8][0] + acc[n8][1] * acc[n8][1];
        s1 += acc[n8][2] * acc[n8][2] + acc[n8][3] * acc[n8][3];
    }
    s0 += __shfl_xor_sync(0xffffffffu, s0, 1);
    s0 += __shfl_xor_sync(0xffffffffu, s0, 2);
    s1 += __shfl_xor_sync(0xffffffffu, s1, 1);
    s1 += __shfl_xor_sync(0xffffffffu, s1, 2);

    const int rq = lane >> 2;
    const int rl0 = wm * 16 + rq;          // local rows
    const int rl1 = rl0 + 8;
    if ((lane & 3) == 0) {
        red[rl0][wn] = s0;
        red[rl1][wn] = s1;
    }
    __syncthreads();

    const float fs0 = red[rl0][0] + red[rl0][1];
    const float fs1 = red[rl1][0] + red[rl1][1];

    const float invD = 1.0f / (float)ND;
    const float fro0 = sqrtf(fs0 * fs0 * invD * invD + 2.0f * fs0 * invD + (float)ND);
    const float fro1 = sqrtf(fs1 * fs1 * invD * invD + 2.0f * fs1 * invD + (float)ND);
    const float inv0 = 1.0f / (sqrtf((fs0 * fs0 * invD + fs0) / (fro0 + EPSF)) + EPSF);
    const float inv1 = 1.0f / (sqrtf((fs1 * fs1 * invD + fs1) / (fro1 + EPSF)) + EPSF);

    const int r0 = i0 + rl0;
    const int r1 = i0 + rl1;

    if (wn == 0 && (lane & 3) == 0) {
        float* sq = which ? g_ksq : g_qsq;
        sq[r0] = fs0 * inv0 * inv0;
        sq[r1] = fs1 * inv1 * inv1;
    }

    __half* outH = which ? g_kn_hi : g_qn_hi;
#pragma unroll
    for (int n8 = 0; n8 < 8; n8++) {
        const int col = wn * 64 + n8 * 8 + cq;
        *(uint32_t*)&outH[(size_t)r0 * ND + col] =
            pack_h2(__float2half(acc[n8][0] * inv0), __float2half(acc[n8][1] * inv0));
        *(uint32_t*)&outH[(size_t)r1 * ND + col] =
            pack_h2(__float2half(acc[n8][2] * inv1), __float2half(acc[n8][3] * inv1));
    }
}

// ---------------------------------------------------------------------------
// Kernel B: single-product fp16 HMMA Gram + fused exp-logit epilogue
// (approx sqrt/div) + per-warp partial row sums into g_psum.
// Stage = 2 matrices (qn_hi, kn_hi). CTA 128x128, 8 warps (4M x 2N).
// ---------------------------------------------------------------------------
#define STAGE_BYTES (2 * MAT_BYTES)
#define GRAM_SMEM (2 * STAGE_BYTES)   // 40960

__device__ __forceinline__ void issue_chunk(uint32_t sbase, int st, int kc,
                                            int i0, int j0, int tid)
{
    const uint32_t stb = sbase + (uint32_t)(st * STAGE_BYTES);
#pragma unroll
    for (int it = 0; it < 2; it++) {
        const int t = it * 256 + tid;
        const int row = t >> 2;
        const int seg = t & 3;
        const uint32_t soff = (uint32_t)(row * 80 + seg * 16);
        const size_t gi = (size_t)(i0 + row) * ND + kc * 32 + seg * 8;
        const size_t gj = (size_t)(j0 + row) * ND + kc * 32 + seg * 8;
        cp16(stb + 0 * MAT_BYTES + soff, &g_qn_hi[gi]);
        cp16(stb + 1 * MAT_BYTES + soff, &g_kn_hi[gj]);
    }
}

__global__ __launch_bounds__(256, 2) void gram_exp_kernel(float* __restrict__ out)
{
    extern __shared__ __align__(16) char dsm[];
    __shared__ float ks_s[128];
    __shared__ float qs_s[128];

    const int tid = threadIdx.x;
    const int lane = tid & 31;
    const int w = tid >> 5;
    const int wm = w & 3;
    const int wn = w >> 2;
    const int i0 = blockIdx.y * 128;
    const int j0 = blockIdx.x * 128;

    if (tid < 128) ks_s[tid] = g_ksq[j0 + tid];
    else           qs_s[tid - 128] = g_qsq[i0 + tid - 128];

    const uint32_t sbase = smem_u32(dsm);

    issue_chunk(sbase, 0, 0, i0, j0, tid); cp_commit();
    issue_chunk(sbase, 1, 1, i0, j0, tid); cp_commit();

    float acc[2][8][4];
#pragma unroll
    for (int mt = 0; mt < 2; mt++)
#pragma unroll
        for (int n8 = 0; n8 < 8; n8++)
#pragma unroll
            for (int q = 0; q < 4; q++) acc[mt][n8][q] = 0.f;

    const int a_row = lane & 15;
    const int a_kh = lane >> 4;
    const int b_n = (lane & 7) | ((lane >> 1) & 8);
    const int b_kh = (lane >> 3) & 1;

#pragma unroll
    for (int kc = 0; kc < 4; kc++) {
        if (kc < 3) cp_wait1(); else cp_wait0();
        __syncthreads();

        const uint32_t stb = sbase + (uint32_t)((kc & 1) * STAGE_BYTES);
        const uint32_t ashi = stb + 0 * MAT_BYTES;
        const uint32_t bshi = stb + 1 * MAT_BYTES;

#pragma unroll
        for (int ks = 0; ks < 2; ks++) {
            const int k0 = ks * 16;
            const uint32_t a_off =
                (uint32_t)(((wm * 32 + a_row) * SSTRIDE + k0 + a_kh * 8) * 2);
            const uint32_t b_off0 =
                (uint32_t)(((wn * 64 + b_n) * SSTRIDE + k0 + b_kh * 8) * 2);

            uint32_t ahi[2][4], bf[4][4];
#pragma unroll
            for (int mt = 0; mt < 2; mt++)
                ldsm4(ahi[mt], ashi + a_off + (uint32_t)(mt * 16 * SSTRIDE * 2));
#pragma unroll
            for (int nt = 0; nt < 4; nt++)
                ldsm4(bf[nt], bshi + b_off0 + (uint32_t)(nt * 16 * SSTRIDE * 2));

#pragma unroll
            for (int mt = 0; mt < 2; mt++)
#pragma unroll
                for (int nt = 0; nt < 4; nt++) {
                    mma_f16(acc[mt][nt * 2 + 0], ahi[mt], &bf[nt][0]);
                    mma_f16(acc[mt][nt * 2 + 1], ahi[mt], &bf[nt][2]);
                }
        }
        __syncthreads();
        if (kc < 2) { issue_chunk(sbase, kc & 1, kc + 2, i0, j0, tid); cp_commit(); }
    }

    // Epilogue + partial row sums (approx math).
    const int rq = lane >> 2;
    const int cq = (lane & 3) * 2;
    float rs[2][2];
    rs[0][0] = rs[0][1] = rs[1][0] = rs[1][1] = 0.f;

#pragma unroll
    for (int mt = 0; mt < 2; mt++) {
        const int rl0 = wm * 32 + mt * 16 + rq;
        const float qs0 = qs_s[rl0];
        const float qs1 = qs_s[rl0 + 8];
#pragma unroll
        for (int n8 = 0; n8 < 8; n8++) {
            const int cl = wn * 64 + n8 * 8 + cq;
            const float k0v = ks_s[cl], k1v = ks_s[cl + 1];
            const float* a = acc[mt][n8];

            float d00 = fmaxf(qs0 + k0v - 2.0f * a[0], 0.0f);
            float d01 = fmaxf(qs0 + k1v - 2.0f * a[1], 0.0f);
            float d10 = fmaxf(qs1 + k0v - 2.0f * a[2], 0.0f);
            float d11 = fmaxf(qs1 + k1v - 2.0f * a[3], 0.0f);

            float2 e0, e1;
            e0.x = __expf(__fdividef(TEMPF, 1.0f + fsqrt_ap(d00)));
            e0.y = __expf(__fdividef(TEMPF, 1.0f + fsqrt_ap(d01)));
            e1.x = __expf(__fdividef(TEMPF, 1.0f + fsqrt_ap(d10)));
            e1.y = __expf(__fdividef(TEMPF, 1.0f + fsqrt_ap(d11)));

            rs[mt][0] += e0.x + e0.y;
            rs[mt][1] += e1.x + e1.y;

            *(float2*)&out[(size_t)(i0 + rl0) * NB + j0 + cl] = e0;
            *(float2*)&out[(size_t)(i0 + rl0 + 8) * NB + j0 + cl] = e1;
        }
    }

    // Reduce partial sums over the 4 lanes sharing a row; store to g_psum.
#pragma unroll
    for (int mt = 0; mt < 2; mt++)
#pragma unroll
        for (int h = 0; h < 2; h++) {
            float s = rs[mt][h];
            s += __shfl_xor_sync(0xffffffffu, s, 1);
            s += __shfl_xor_sync(0xffffffffu, s, 2);
            if ((lane & 3) == 0) {
                const int row = i0 + wm * 32 + mt * 16 + rq + h * 8;
                g_psum[(size_t)row * 64 + blockIdx.x * 2 + wn] = s;
            }
        }
}

// ---------------------------------------------------------------------------
// Kernel C: normalize rows using precomputed partial sums. 512 thr / 2 rows.
// ---------------------------------------------------------------------------
__global__ __launch_bounds__(512) void scale_kernel(float* __restrict__ out)
{
    __shared__ float sinv[2];
    const int tid = threadIdx.x;
    const int half = tid >> 8;
    const int t = tid & 255;
    const int row = blockIdx.x * 2 + half;

    float4* p = (float4*)(out + (size_t)row * NB);
    float4 v[4];
#pragma unroll
    for (int q = 0; q < 4; q++) v[q] = p[t + q * 256];

    if (t < 32) {
        float s = g_psum[(size_t)row * 64 + t] + g_psum[(size_t)row * 64 + 32 + t];
#pragma unroll
        for (int o = 16; o > 0; o >>= 1) s += __shfl_xor_sync(0xffffffffu, s, o);
        if (t == 0) sinv[half] = 1.0f / s;
    }
    __syncthreads();
    const float inv = sinv[half];

#pragma unroll
    for (int q = 0; q < 4; q++) {
        v[q].x *= inv; v[q].y *= inv; v[q].z *= inv; v[q].w *= inv;
        p[t + q * 256] = v[q];
    }
}

// ---------------------------------------------------------------------------
// Launch
// ---------------------------------------------------------------------------
extern "C" void kernel_launch(void* const* d_in, const int* in_sizes, int n_in,
                              void* d_out, int out_size)
{
    (void)in_sizes; (void)n_in; (void)out_size;
    const float* qp = (const float*)d_in[0];
    const float* kp = (const float*)d_in[1];
    const float* Wq = (const float*)d_in[2];
    const float* bq = (const float*)d_in[3];
    const float* Wk = (const float*)d_in[4];
    const float* bk = (const float*)d_in[5];
    float* out = (float*)d_out;

    cudaFuncSetAttribute(gram_exp_kernel,
                         cudaFuncAttributeMaxDynamicSharedMemorySize, GRAM_SMEM);

    dim3 gp(NB / PROWS, 2);
    proj_mma_kernel<<<gp, 256>>>(qp, Wq, bq, kp, Wk, bk);

    dim3 g(NB / 128, NB / 128);
    gram_exp_kernel<<<g, 256, GRAM_SMEM>>>(out);

    scale_kernel<<<NB / 2, 512>>>(out);
}